// round 11
// baseline (speedup 1.0000x reference)
#include <cuda_runtime.h>
#include <cuda_bf16.h>
#include <cstdint>
#include <cstddef>

#define NN 4096
#define EE 32768
#define HH 1024
#define PP 4096
#define FF 64

// ======================= portable PTX helpers (no sm_103a-only ops) =======================
__device__ __forceinline__ uint32_t smem_u32(const void* p) {
    uint32_t a;
    asm("{ .reg .u64 t; cvta.to.shared.u64 t, %1; cvt.u32.u64 %0, t; }" : "=r"(a) : "l"(p));
    return a;
}
__device__ __forceinline__ void ldsm_x4(uint32_t* r, uint32_t addr) {
    asm volatile("ldmatrix.sync.aligned.m8n8.x4.shared.b16 {%0,%1,%2,%3}, [%4];"
        : "=r"(r[0]), "=r"(r[1]), "=r"(r[2]), "=r"(r[3]) : "r"(addr));
}
// NON-trans: B stored [N][K] k-contiguous matches the row.col mma B fragment.
__device__ __forceinline__ void ldsm_x2(uint32_t* r, uint32_t addr) {
    asm volatile("ldmatrix.sync.aligned.m8n8.x2.shared.b16 {%0,%1}, [%2];"
        : "=r"(r[0]), "=r"(r[1]) : "r"(addr));
}
__device__ __forceinline__ void mma_bf16(float* c, const uint32_t* a, const uint32_t* b) {
    asm volatile("mma.sync.aligned.m16n8k16.row.col.f32.bf16.bf16.f32 "
        "{%0,%1,%2,%3}, {%4,%5,%6,%7}, {%8,%9}, {%0,%1,%2,%3};"
        : "+f"(c[0]), "+f"(c[1]), "+f"(c[2]), "+f"(c[3])
        : "r"(a[0]), "r"(a[1]), "r"(a[2]), "r"(a[3]), "r"(b[0]), "r"(b[1]));
}
__device__ __forceinline__ uint32_t pack_bf16(float v0, float v1) {
    __nv_bfloat162 h = __floats2bfloat162_rn(v0, v1);
    return *reinterpret_cast<uint32_t*>(&h);
}
__device__ __forceinline__ void cp_async16(uint32_t saddr, const void* gptr) {
    asm volatile("cp.async.cg.shared.global [%0], [%1], 16;" :: "r"(saddr), "l"(gptr));
}
#define CP_COMMIT() asm volatile("cp.async.commit_group;" ::: "memory")
#define CP_WAIT0()  asm volatile("cp.async.wait_group 0;" ::: "memory")

// ======================= device scratch =======================
__device__ float g_obj0[NN * HH];
__device__ float g_objA[NN * HH];
__device__ float g_rel0[EE * HH];
__device__ float g_relA[EE * HH];
__device__ float g_relmsg[EE * HH];
__device__ float g_objmsg[NN * HH];
__device__ float g_accS[NN * HH];
__device__ float g_accO[NN * HH];
__device__ float g_cntS[NN];
__device__ float g_cntO[NN];
__device__ float g_rsumR[EE];
__device__ float g_rsqR[EE];
__device__ float g_rsumO[NN];
__device__ float g_rsqO[NN];
__device__ float g_muS[EE];
__device__ float g_rsS[EE];
__device__ float g_muO[EE];
__device__ float g_rsO[EE];
__device__ float g_gate0[EE];
__device__ float g_gate1[EE];
__device__ float g_gate2[EE];
__device__ float g_gate3[EE];
__device__ float g_gateout[EE * FF];
// pre-transposed + bf16-split weights ([N][K] row-major)
__device__ __nv_bfloat16 g_wdobj_hi[HH * PP];
__device__ __nv_bfloat16 g_wdobj_lo[HH * PP];
__device__ __nv_bfloat16 g_wdrel_hi[HH * PP];
__device__ __nv_bfloat16 g_wdrel_lo[HH * PP];
__device__ __nv_bfloat16 g_wg_hi[4 * FF * 2 * HH];
__device__ __nv_bfloat16 g_wg_lo[4 * FF * 2 * HH];
__device__ __nv_bfloat16 g_wf_hi[4 * HH * HH];  // wih_objf, whh_objf, wih_relf, whh_relf
__device__ __nv_bfloat16 g_wf_lo[4 * HH * HH];

// ======================= weight prep: W[K,N] -> hi/lo bf16 [N][K] =======================
__global__ void transpose_split(const float* __restrict__ W, int K, int N,
                                __nv_bfloat16* __restrict__ hi, __nv_bfloat16* __restrict__ lo)
{
    __shared__ float tile[32][33];
    int n0 = blockIdx.x * 32, k0 = blockIdx.y * 32;
    int tx = threadIdx.x, ty = threadIdx.y;   // (32, 8)
#pragma unroll
    for (int i = 0; i < 32; i += 8)
        tile[ty + i][tx] = W[(size_t)(k0 + ty + i) * N + n0 + tx];
    __syncthreads();
#pragma unroll
    for (int i = 0; i < 32; i += 8) {
        float v = tile[tx][ty + i];
        __nv_bfloat16 h = __float2bfloat16_rn(v);
        size_t o = (size_t)(n0 + ty + i) * K + k0 + tx;
        hi[o] = h;
        lo[o] = __float2bfloat16_rn(v - __bfloat162float(h));
    }
}

// ======================= bf16x3 mma.sync GEMM (BK=64, cp.async B) =======================
// C[M,N] = f(A) @ B^T + bias1 (+bias2), f = id / relu / relu(LN(.)), virtual K = K1(+K2).
// A fp32 (optionally row-gathered); B pre-split bf16 hi/lo, [N][ldB] row-major.
template<int BN, bool DUAL, bool RELU_A, bool LN>
__global__ __launch_bounds__(256, 1)
void gemm_mma(const float* __restrict__ A1, const int* __restrict__ idx1, int ldA1, int K1,
              const float* __restrict__ A2, const int* __restrict__ idx2, int ldA2, int K2,
              const __nv_bfloat16* __restrict__ Bhi1, const __nv_bfloat16* __restrict__ Blo1, int ldB1,
              const __nv_bfloat16* __restrict__ Bhi2, const __nv_bfloat16* __restrict__ Blo2, int ldB2,
              const float* __restrict__ mu, const float* __restrict__ rsg,
              const float* __restrict__ lng, const float* __restrict__ lnb,
              const float* __restrict__ bias1, const float* __restrict__ bias2,
              float* __restrict__ C, int ldC, int reluC)
{
    constexpr int BK = 64;
    constexpr int WARPS_M = (BN == 128) ? 2 : 4;
    constexpr int WM = 128 / WARPS_M;          // 64 or 32
    constexpr int MT = WM / 16;                // 4 or 2
    constexpr int NT = 4;                      // WN = 32
    constexpr int AST = 72;                    // smem row stride in halves (144B, 16B-aligned)
    constexpr int A_HALVES = 128 * AST;
    constexpr int B_HALVES = BN * AST;
    constexpr int STAGE = 2 * A_HALVES + 2 * B_HALVES;  // hi+lo for A and B
    constexpr int NBC = (BN * 8) / 256;        // cp.async 16B chunks per thread per B tile

    extern __shared__ __nv_bfloat16 sm[];
    const int t = threadIdx.x;
    const int wid = t >> 5, lane = t & 31;
    const int wm = wid % WARPS_M, wn = wid / WARPS_M;

    const int blockM = blockIdx.y * 128;
    const int n0 = blockIdx.x * BN;

    // ---- producer setup: 2 threads per A row, 32 floats each ----
    const int arow = t >> 1, ahalf = t & 1;
    const int row_m = blockM + arow;
    int r1 = row_m, r2 = row_m;
    if (LN) { if (idx1) r1 = idx1[row_m]; if (idx2) r2 = idx2[row_m]; }
    float mu_t = 0.f, rs_t = 0.f;
    if (LN) { mu_t = mu[row_m]; rs_t = rsg[row_m]; }
    const float* rowA1 = A1 + (size_t)r1 * ldA1;
    const float* rowA2 = DUAL ? (A2 + (size_t)r2 * ldA2) : A1;

    const int nChunks = (K1 + (DUAL ? K2 : 0)) / BK;

    // ---- per-lane ldmatrix offsets ----
    const int a_row_off = (lane & 7) | (((lane >> 3) & 1) << 3);
    const int a_kh = (lane >> 4) << 3;
    const int b_row_off = lane & 7;
    const int b_kh = ((lane >> 3) & 1) << 3;

    float acc[MT][NT][4];
#pragma unroll
    for (int i = 0; i < MT; i++)
#pragma unroll
        for (int j = 0; j < NT; j++)
#pragma unroll
            for (int k = 0; k < 4; k++) acc[i][j][k] = 0.f;

    // A staging registers (32 floats per thread)
    float fA[32];

    auto loadA = [&](int c) {
        int k0v = c * BK;
        bool fh = (!DUAL) || (k0v < K1);
        const float* src = (fh ? rowA1 + k0v : rowA2 + (k0v - K1)) + ahalf * 32;
        int jb = k0v + ahalf * 32;
#pragma unroll
        for (int q = 0; q < 8; q++) {
            float4 v = ((const float4*)src)[q];
            if (LN) {
                int j = jb + q * 4;
                float4 g = *(const float4*)(lng + j);
                float4 bb = *(const float4*)(lnb + j);
                v.x = fmaxf(fmaf((v.x - mu_t) * rs_t, g.x, bb.x), 0.f);
                v.y = fmaxf(fmaf((v.y - mu_t) * rs_t, g.y, bb.y), 0.f);
                v.z = fmaxf(fmaf((v.z - mu_t) * rs_t, g.z, bb.z), 0.f);
                v.w = fmaxf(fmaf((v.w - mu_t) * rs_t, g.w, bb.w), 0.f);
            } else if (RELU_A) {
                v.x = fmaxf(v.x, 0.f); v.y = fmaxf(v.y, 0.f);
                v.z = fmaxf(v.z, 0.f); v.w = fmaxf(v.w, 0.f);
            }
            fA[q * 4 + 0] = v.x; fA[q * 4 + 1] = v.y;
            fA[q * 4 + 2] = v.z; fA[q * 4 + 3] = v.w;
        }
    };
    // async copy both B tiles (hi+lo) for chunk c into buffer buf
    auto issueB = [&](int c, int buf) {
        int k0v = c * BK;
        bool fh = (!DUAL) || (k0v < K1);
        const __nv_bfloat16* bh = fh ? Bhi1 : Bhi2;
        const __nv_bfloat16* bl = fh ? Blo1 : Blo2;
        int ldB = fh ? ldB1 : ldB2;
        int kk = fh ? k0v : (k0v - K1);
        uint32_t sB = smem_u32(sm + buf * STAGE + 2 * A_HALVES);
        uint32_t sBlo = sB + B_HALVES * 2;
#pragma unroll
        for (int i = 0; i < NBC; i++) {
            int idx = t + i * 256;
            int row = idx >> 3, q = idx & 7;    // 8 x 16B chunks per 64-half row
            size_t go = (size_t)(n0 + row) * ldB + kk + q * 8;
            uint32_t so = (uint32_t)(row * AST + q * 8) * 2;
            cp_async16(sB + so, bh + go);
            cp_async16(sBlo + so, bl + go);
        }
    };
    auto storeA = [&](int buf) {
        __nv_bfloat16* sA = sm + buf * STAGE;
        __nv_bfloat16* sAlo = sA + A_HALVES;
        int base = arow * AST + ahalf * 32;
#pragma unroll
        for (int g4 = 0; g4 < 4; g4++) {
            uint32_t h[4], l[4];
#pragma unroll
            for (int i = 0; i < 4; i++) {
                float v0 = fA[g4 * 8 + 2 * i], v1 = fA[g4 * 8 + 2 * i + 1];
                __nv_bfloat16 h0 = __float2bfloat16_rn(v0), h1 = __float2bfloat16_rn(v1);
                __nv_bfloat162 hp; hp.x = h0; hp.y = h1;
                h[i] = *reinterpret_cast<uint32_t*>(&hp);
                l[i] = pack_bf16(v0 - __bfloat162float(h0), v1 - __bfloat162float(h1));
            }
            *(uint4*)(sA + base + g4 * 8)   = make_uint4(h[0], h[1], h[2], h[3]);
            *(uint4*)(sAlo + base + g4 * 8) = make_uint4(l[0], l[1], l[2], l[3]);
        }
    };
    auto domma = [&](int buf) {
        uint32_t aHi = smem_u32(sm + buf * STAGE);
        uint32_t aLo = aHi + A_HALVES * 2;
        uint32_t bHi = aHi + 2 * A_HALVES * 2;
        uint32_t bLo = bHi + B_HALVES * 2;
#pragma unroll
        for (int ks = 0; ks < 4; ks++) {
            uint32_t ah[MT][4], al[MT][4], bh[NT][2], bl[NT][2];
#pragma unroll
            for (int mt = 0; mt < MT; mt++) {
                uint32_t off = (uint32_t)((wm * WM + mt * 16 + a_row_off) * AST + ks * 16 + a_kh) * 2;
                ldsm_x4(ah[mt], aHi + off);
                ldsm_x4(al[mt], aLo + off);
            }
#pragma unroll
            for (int nt = 0; nt < NT; nt++) {
                uint32_t off = (uint32_t)((wn * 32 + nt * 8 + b_row_off) * AST + ks * 16 + b_kh) * 2;
                ldsm_x2(bh[nt], bHi + off);
                ldsm_x2(bl[nt], bLo + off);
            }
#pragma unroll
            for (int mt = 0; mt < MT; mt++)
#pragma unroll
                for (int nt = 0; nt < NT; nt++) mma_bf16(acc[mt][nt], ah[mt], bh[nt]);
#pragma unroll
            for (int mt = 0; mt < MT; mt++)
#pragma unroll
                for (int nt = 0; nt < NT; nt++) mma_bf16(acc[mt][nt], ah[mt], bl[nt]);
#pragma unroll
            for (int mt = 0; mt < MT; mt++)
#pragma unroll
                for (int nt = 0; nt < NT; nt++) mma_bf16(acc[mt][nt], al[mt], bh[nt]);
        }
    };

    // ---- pipeline: B via cp.async overlaps domma; A via registers ----
    loadA(0);
    issueB(0, 0);
    CP_COMMIT();
    storeA(0);
    CP_WAIT0();
    __syncthreads();
    for (int c = 0; c < nChunks; c++) {
        if (c + 1 < nChunks) {
            loadA(c + 1);
            issueB(c + 1, (c + 1) & 1);
            CP_COMMIT();
        }
        domma(c & 1);
        if (c + 1 < nChunks) storeA((c + 1) & 1);
        CP_WAIT0();
        __syncthreads();
    }

    // ---- epilogue ----
#pragma unroll
    for (int nt = 0; nt < NT; nt++) {
        int col = n0 + wn * 32 + nt * 8 + (lane & 3) * 2;
        float b0 = bias1 ? bias1[col] : 0.f;
        float b1 = bias1 ? bias1[col + 1] : 0.f;
        if (bias2) { b0 += bias2[col]; b1 += bias2[col + 1]; }
#pragma unroll
        for (int mt = 0; mt < MT; mt++) {
            int r0 = blockM + wm * WM + mt * 16 + (lane >> 2);
            float2 o0, o1;
            o0.x = acc[mt][nt][0] + b0; o0.y = acc[mt][nt][1] + b1;
            o1.x = acc[mt][nt][2] + b0; o1.y = acc[mt][nt][3] + b1;
            if (reluC) {
                o0.x = fmaxf(o0.x, 0.f); o0.y = fmaxf(o0.y, 0.f);
                o1.x = fmaxf(o1.x, 0.f); o1.y = fmaxf(o1.y, 0.f);
            }
            *(float2*)(C + (size_t)r0 * ldC + col) = o0;
            *(float2*)(C + (size_t)(r0 + 8) * ldC + col) = o1;
        }
    }
}

// ======================= gate reduce: gate[e] = mean_f sigmoid(X[e,f]) =======================
__global__ void gate_reduce(const float* __restrict__ X, float* __restrict__ gate)
{
    int row = blockIdx.x * 8 + (threadIdx.x >> 5);
    int lane = threadIdx.x & 31;
    float2 v = ((const float2*)(X + (size_t)row * FF))[lane];
    float s = 1.f / (1.f + __expf(-v.x)) + 1.f / (1.f + __expf(-v.y));
#pragma unroll
    for (int o = 16; o > 0; o >>= 1) s += __shfl_down_sync(0xffffffffu, s, o);
    if (lane == 0) gate[row] = s * (1.f / (float)FF);
}

// ======================= elementwise kernels (validated in R2) =======================
__global__ void rowstats_kernel(const float* __restrict__ X, float* __restrict__ sum,
                                float* __restrict__ sq, int rows)
{
    int row = blockIdx.x * 8 + (threadIdx.x >> 5);
    int lane = threadIdx.x & 31;
    if (row >= rows) return;
    const float4* p = (const float4*)(X + (size_t)row * HH);
    float s = 0.f, q = 0.f;
#pragma unroll
    for (int i = 0; i < 8; i++) {
        float4 v = p[lane + (i << 5)];
        s += v.x + v.y + v.z + v.w;
        q += v.x * v.x + v.y * v.y + v.z * v.z + v.w * v.w;
    }
#pragma unroll
    for (int o = 16; o > 0; o >>= 1) {
        s += __shfl_down_sync(0xffffffffu, s, o);
        q += __shfl_down_sync(0xffffffffu, q, o);
    }
    if (lane == 0) { sum[row] = s; sq[row] = q; }
}

__global__ void edge_stats_kernel(const int* __restrict__ sub, const int* __restrict__ obj,
    const float* __restrict__ sR, const float* __restrict__ qR,
    const float* __restrict__ sO, const float* __restrict__ qO,
    float* __restrict__ muS, float* __restrict__ rsS,
    float* __restrict__ muO, float* __restrict__ rsO)
{
    int e = blockIdx.x * 256 + threadIdx.x;
    if (e >= EE) return;
    float sr = sR[e], qr = qR[e];
    {
        int n = sub[e];
        float s = sr + sO[n], q = qr + qO[n];
        float m = s * (1.f / 2048.f);
        float v = q * (1.f / 2048.f) - m * m;
        muS[e] = m; rsS[e] = rsqrtf(v + 1e-5f);
    }
    {
        int n = obj[e];
        float s = sr + sO[n], q = qr + qO[n];
        float m = s * (1.f / 2048.f);
        float v = q * (1.f / 2048.f) - m * m;
        muO[e] = m; rsO[e] = rsqrtf(v + 1e-5f);
    }
}

__global__ void rel_msg_kernel(const float* __restrict__ obj,
                               const int* __restrict__ sub, const int* __restrict__ objx,
                               const float* __restrict__ gS, const float* __restrict__ gO,
                               float* __restrict__ out)
{
    int i = blockIdx.x * 256 + threadIdx.x;
    int e = i >> 8;
    int h4 = (i & 255) << 2;
    float4 a = *(const float4*)(obj + (size_t)sub[e]  * HH + h4);
    float4 b = *(const float4*)(obj + (size_t)objx[e] * HH + h4);
    float ga = 0.5f * gS[e], gb = 0.5f * gO[e];
    float4 r;
    r.x = ga * a.x + gb * b.x;
    r.y = ga * a.y + gb * b.y;
    r.z = ga * a.z + gb * b.z;
    r.w = ga * a.w + gb * b.w;
    *(float4*)(out + (size_t)e * HH + h4) = r;
}

__global__ void scatter_kernel(const float* __restrict__ rel,
                               const int* __restrict__ sub, const int* __restrict__ objx,
                               const float* __restrict__ gS, const float* __restrict__ gO,
                               float* __restrict__ accS, float* __restrict__ accO)
{
    int i = blockIdx.x * 256 + threadIdx.x;
    int e = i >> 8;
    int h4 = (i & 255) << 2;
    float4 v = *(const float4*)(rel + (size_t)e * HH + h4);
    float gs = gS[e], go = gO[e];
    float* ps = accS + (size_t)sub[e] * HH + h4;
    atomicAdd(ps + 0, v.x * gs);
    atomicAdd(ps + 1, v.y * gs);
    atomicAdd(ps + 2, v.z * gs);
    atomicAdd(ps + 3, v.w * gs);
    float* po = accO + (size_t)objx[e] * HH + h4;
    atomicAdd(po + 0, v.x * go);
    atomicAdd(po + 1, v.y * go);
    atomicAdd(po + 2, v.z * go);
    atomicAdd(po + 3, v.w * go);
}

__global__ void objmsg_kernel(const float* __restrict__ accS, const float* __restrict__ accO,
                              const float* __restrict__ cS, const float* __restrict__ cO,
                              float* __restrict__ out)
{
    int i = blockIdx.x * 256 + threadIdx.x;
    int n = i >> 8;
    int h4 = (i & 255) << 2;
    float rs_ = 0.5f / fmaxf(cS[n], 1.f);
    float ro_ = 0.5f / fmaxf(cO[n], 1.f);
    float4 a = *(const float4*)(accS + (size_t)n * HH + h4);
    float4 b = *(const float4*)(accO + (size_t)n * HH + h4);
    float4 r;
    r.x = rs_ * a.x + ro_ * b.x;
    r.y = rs_ * a.y + ro_ * b.y;
    r.z = rs_ * a.z + ro_ * b.z;
    r.w = rs_ * a.w + ro_ * b.w;
    *(float4*)(out + (size_t)n * HH + h4) = r;
}

__global__ void zero_kernel(float* __restrict__ p, int n4)
{
    int i = blockIdx.x * 256 + threadIdx.x;
    if (i < n4) *(float4*)(p + (size_t)i * 4) = make_float4(0.f, 0.f, 0.f, 0.f);
}

__global__ void count_kernel(const int* __restrict__ sub, const int* __restrict__ objx,
                             float* __restrict__ cS, float* __restrict__ cO)
{
    int e = blockIdx.x * 256 + threadIdx.x;
    if (e < EE) {
        atomicAdd(&cS[sub[e]], 1.f);
        atomicAdd(&cO[objx[e]], 1.f);
    }
}

// ======================= host driver =======================
template<typename T>
static T* symaddrT(const void* sym)
{
    void* p = nullptr;
    cudaGetSymbolAddress(&p, sym);
    return (T*)p;
}

extern "C" void kernel_launch(void* const* d_in, const int* in_sizes, int n_in,
                              void* d_out, int out_size)
{
    const float* obj_feat   = (const float*)d_in[0];
    const float* rel_feat   = (const float*)d_in[1];
    const int*   sub_idx    = (const int*)d_in[2];
    const int*   obj_idx    = (const int*)d_in[3];
    const float* w_obj_down = (const float*)d_in[4];
    const float* b_obj_down = (const float*)d_in[5];
    const float* w_rel_down = (const float*)d_in[6];
    const float* b_rel_down = (const float*)d_in[7];
    const float *ln_g[4], *ln_b[4], *w_m[4], *b_m[4];
    for (int m = 0; m < 4; m++) {       // 0=s2p, 1=o2p, 2=p2s, 3=p2o
        ln_g[m] = (const float*)d_in[8 + 4 * m];
        ln_b[m] = (const float*)d_in[9 + 4 * m];
        w_m[m]  = (const float*)d_in[10 + 4 * m];
        b_m[m]  = (const float*)d_in[11 + 4 * m];
    }
    const float* wf[4]  = { (const float*)d_in[24], (const float*)d_in[26],
                            (const float*)d_in[28], (const float*)d_in[30] };
    const float* bih_objf = (const float*)d_in[25];
    const float* bhh_objf = (const float*)d_in[27];
    const float* bih_relf = (const float*)d_in[29];
    const float* bhh_relf = (const float*)d_in[31];
    float* out = (float*)d_out;

    float* obj0    = symaddrT<float>(g_obj0);
    float* objA    = symaddrT<float>(g_objA);
    float* rel0    = symaddrT<float>(g_rel0);
    float* relA    = symaddrT<float>(g_relA);
    float* relmsg  = symaddrT<float>(g_relmsg);
    float* objmsg  = symaddrT<float>(g_objmsg);
    float* accS    = symaddrT<float>(g_accS);
    float* accO    = symaddrT<float>(g_accO);
    float* cntS    = symaddrT<float>(g_cntS);
    float* cntO    = symaddrT<float>(g_cntO);
    float* rsumR   = symaddrT<float>(g_rsumR);
    float* rsqR    = symaddrT<float>(g_rsqR);
    float* rsumO   = symaddrT<float>(g_rsumO);
    float* rsqO    = symaddrT<float>(g_rsqO);
    float* muS     = symaddrT<float>(g_muS);
    float* rsS     = symaddrT<float>(g_rsS);
    float* muO     = symaddrT<float>(g_muO);
    float* rsO     = symaddrT<float>(g_rsO);
    float* gateout = symaddrT<float>(g_gateout);
    float* gate[4] = { symaddrT<float>(g_gate0), symaddrT<float>(g_gate1),
                       symaddrT<float>(g_gate2), symaddrT<float>(g_gate3) };
    __nv_bfloat16* wdobj_hi = symaddrT<__nv_bfloat16>(g_wdobj_hi);
    __nv_bfloat16* wdobj_lo = symaddrT<__nv_bfloat16>(g_wdobj_lo);
    __nv_bfloat16* wdrel_hi = symaddrT<__nv_bfloat16>(g_wdrel_hi);
    __nv_bfloat16* wdrel_lo = symaddrT<__nv_bfloat16>(g_wdrel_lo);
    __nv_bfloat16* wg_hi    = symaddrT<__nv_bfloat16>(g_wg_hi);
    __nv_bfloat16* wg_lo    = symaddrT<__nv_bfloat16>(g_wg_lo);
    __nv_bfloat16* wf_hi    = symaddrT<__nv_bfloat16>(g_wf_hi);
    __nv_bfloat16* wf_lo    = symaddrT<__nv_bfloat16>(g_wf_lo);

    // ---- weight prep ----
    {
        dim3 blk(32, 8);
        transpose_split<<<dim3(HH / 32, PP / 32), blk>>>(w_obj_down, PP, HH, wdobj_hi, wdobj_lo);
        transpose_split<<<dim3(HH / 32, PP / 32), blk>>>(w_rel_down, PP, HH, wdrel_hi, wdrel_lo);
        for (int m = 0; m < 4; m++)
            transpose_split<<<dim3(FF / 32, 2 * HH / 32), blk>>>(
                w_m[m], 2 * HH, FF,
                wg_hi + (size_t)m * FF * 2 * HH, wg_lo + (size_t)m * FF * 2 * HH);
        for (int m = 0; m < 4; m++)
            transpose_split<<<dim3(HH / 32, HH / 32), blk>>>(
                wf[m], HH, HH,
                wf_hi + (size_t)m * HH * HH, wf_lo + (size_t)m * HH * HH);
    }

    // dynamic smem: double-buffered (A hi/lo + B hi/lo), BK=64, 144B rows
    constexpr int SM128 = 2 * (2 * 128 * 72 + 2 * 128 * 72) * 2;   // 147456 B
    constexpr int SM64  = 2 * (2 * 128 * 72 + 2 * 64 * 72) * 2;    // 110592 B
    auto kPlain = gemm_mma<128, false, false, false>;
    auto kFuse  = gemm_mma<128, true,  true,  false>;
    auto kGate  = gemm_mma<64,  true,  false, true>;
    cudaFuncSetAttribute(kPlain, cudaFuncAttributeMaxDynamicSharedMemorySize, SM128);
    cudaFuncSetAttribute(kFuse,  cudaFuncAttributeMaxDynamicSharedMemorySize, SM128);
    cudaFuncSetAttribute(kGate,  cudaFuncAttributeMaxDynamicSharedMemorySize, SM64);

    // ---- down-dim projections: relu(X @ Wd + b) ----
    kPlain<<<dim3(HH / 128, NN / 128), 256, SM128>>>(
        obj_feat, nullptr, PP, PP, nullptr, nullptr, 0, 0,
        wdobj_hi, wdobj_lo, PP, nullptr, nullptr, 0,
        nullptr, nullptr, nullptr, nullptr,
        b_obj_down, nullptr, obj0, HH, 1);
    kPlain<<<dim3(HH / 128, EE / 128), 256, SM128>>>(
        rel_feat, nullptr, PP, PP, nullptr, nullptr, 0, 0,
        wdrel_hi, wdrel_lo, PP, nullptr, nullptr, 0,
        nullptr, nullptr, nullptr, nullptr,
        b_rel_down, nullptr, rel0, HH, 1);

    // ---- per-node edge counts ----
    zero_kernel<<<(NN / 4 + 255) / 256, 256>>>(cntS, NN / 4);
    zero_kernel<<<(NN / 4 + 255) / 256, 256>>>(cntO, NN / 4);
    count_kernel<<<EE / 256, 256>>>(sub_idx, obj_idx, cntS, cntO);

    float* objCur = obj0;
    float* relCur = rel0;
    for (int it = 0; it < 2; it++) {
        float* objNext = (it == 0) ? objA : out;
        float* relNext = (it == 0) ? relA : out + (size_t)NN * HH;

        // LN stats (shared across the 4 MPUs)
        rowstats_kernel<<<EE / 8, 256>>>(relCur, rsumR, rsqR, EE);
        rowstats_kernel<<<NN / 8, 256>>>(objCur, rsumO, rsqO, NN);
        edge_stats_kernel<<<EE / 256, 256>>>(sub_idx, obj_idx, rsumR, rsqR,
                                             rsumO, rsqO, muS, rsS, muO, rsO);

        // gates: concat order (first, second); LN+relu fused into A producer
        const float* fsrc[4]  = { relCur, relCur, objCur, objCur };
        const int*   fidx[4]  = { nullptr, nullptr, sub_idx, obj_idx };
        const float* ssrc[4]  = { objCur, objCur, relCur, relCur };
        const int*   sidx[4]  = { sub_idx, obj_idx, nullptr, nullptr };
        const float* gmu[4]   = { muS, muO, muS, muO };
        const float* grs[4]   = { rsS, rsO, rsS, rsO };
        for (int m = 0; m < 4; m++) {
            kGate<<<dim3(1, EE / 128), 256, SM64>>>(
                fsrc[m], fidx[m], HH, HH, ssrc[m], sidx[m], HH, HH,
                wg_hi + (size_t)m * FF * 2 * HH, wg_lo + (size_t)m * FF * 2 * HH, 2 * HH,
                wg_hi + (size_t)m * FF * 2 * HH + HH, wg_lo + (size_t)m * FF * 2 * HH + HH, 2 * HH,
                gmu[m], grs[m], ln_g[m], ln_b[m],
                b_m[m], nullptr, gateout, FF, 0);
            gate_reduce<<<EE / 8, 256>>>(gateout, gate[m]);
        }

        // messages
        rel_msg_kernel<<<EE * (HH / 4) / 256, 256>>>(objCur, sub_idx, obj_idx,
                                                     gate[0], gate[1], relmsg);
        zero_kernel<<<(NN * HH / 4 + 255) / 256, 256>>>(accS, NN * HH / 4);
        zero_kernel<<<(NN * HH / 4 + 255) / 256, 256>>>(accO, NN * HH / 4);
        scatter_kernel<<<EE * (HH / 4) / 256, 256>>>(relCur, sub_idx, obj_idx,
                                                     gate[2], gate[3], accS, accO);
        objmsg_kernel<<<NN * (HH / 4) / 256, 256>>>(accS, accO, cntS, cntO, objmsg);

        // fusion: C = relu(msg)@Wih + relu(cur)@Whh + bih + bhh
        kFuse<<<dim3(HH / 128, NN / 128), 256, SM128>>>(
            objmsg, nullptr, HH, HH, objCur, nullptr, HH, HH,
            wf_hi + 0 * (size_t)HH * HH, wf_lo + 0 * (size_t)HH * HH, HH,
            wf_hi + 1 * (size_t)HH * HH, wf_lo + 1 * (size_t)HH * HH, HH,
            nullptr, nullptr, nullptr, nullptr,
            bih_objf, bhh_objf, objNext, HH, 0);
        kFuse<<<dim3(HH / 128, EE / 128), 256, SM128>>>(
            relmsg, nullptr, HH, HH, relCur, nullptr, HH, HH,
            wf_hi + 2 * (size_t)HH * HH, wf_lo + 2 * (size_t)HH * HH, HH,
            wf_hi + 3 * (size_t)HH * HH, wf_lo + 3 * (size_t)HH * HH, HH,
            nullptr, nullptr, nullptr, nullptr,
            bih_relf, bhh_relf, relNext, HH, 0);

        objCur = objNext;
        relCur = relNext;
    }
}

// round 15
// speedup vs baseline: 1.0855x; 1.0855x over previous
#include <cuda_runtime.h>
#include <cuda_bf16.h>
#include <cstdint>
#include <cstddef>

#define NN 4096
#define EE 32768
#define HH 1024
#define PP 4096
#define FF 64

// ======================= portable PTX helpers (no sm_103a-only ops) =======================
__device__ __forceinline__ uint32_t smem_u32(const void* p) {
    uint32_t a;
    asm("{ .reg .u64 t; cvta.to.shared.u64 t, %1; cvt.u32.u64 %0, t; }" : "=r"(a) : "l"(p));
    return a;
}
__device__ __forceinline__ void ldsm_x4(uint32_t* r, uint32_t addr) {
    asm volatile("ldmatrix.sync.aligned.m8n8.x4.shared.b16 {%0,%1,%2,%3}, [%4];"
        : "=r"(r[0]), "=r"(r[1]), "=r"(r[2]), "=r"(r[3]) : "r"(addr));
}
// NON-trans: B stored [N][K] k-contiguous matches the row.col mma B fragment.
__device__ __forceinline__ void ldsm_x2(uint32_t* r, uint32_t addr) {
    asm volatile("ldmatrix.sync.aligned.m8n8.x2.shared.b16 {%0,%1}, [%2];"
        : "=r"(r[0]), "=r"(r[1]) : "r"(addr));
}
__device__ __forceinline__ void mma_bf16(float* c, const uint32_t* a, const uint32_t* b) {
    asm volatile("mma.sync.aligned.m16n8k16.row.col.f32.bf16.bf16.f32 "
        "{%0,%1,%2,%3}, {%4,%5,%6,%7}, {%8,%9}, {%0,%1,%2,%3};"
        : "+f"(c[0]), "+f"(c[1]), "+f"(c[2]), "+f"(c[3])
        : "r"(a[0]), "r"(a[1]), "r"(a[2]), "r"(a[3]), "r"(b[0]), "r"(b[1]));
}
__device__ __forceinline__ uint32_t pack_bf16(float v0, float v1) {
    __nv_bfloat162 h = __floats2bfloat162_rn(v0, v1);
    return *reinterpret_cast<uint32_t*>(&h);
}

// ======================= device scratch =======================
__device__ float g_obj0[NN * HH];
__device__ float g_objA[NN * HH];
__device__ float g_rel0[EE * HH];
__device__ float g_relA[EE * HH];
__device__ float g_relmsg[EE * HH];
__device__ float g_objmsg[NN * HH];
__device__ float g_accS[NN * HH];
__device__ float g_accO[NN * HH];
__device__ float g_cntS[NN];
__device__ float g_cntO[NN];
__device__ float g_rsumR[EE];
__device__ float g_rsqR[EE];
__device__ float g_rsumO[NN];
__device__ float g_rsqO[NN];
__device__ float g_muS[EE];
__device__ float g_rsS[EE];
__device__ float g_muO[EE];
__device__ float g_rsO[EE];
__device__ float g_gate0[EE];
__device__ float g_gate1[EE];
__device__ float g_gate2[EE];
__device__ float g_gate3[EE];
// pre-transposed + bf16-split weights ([N][K] row-major)
__device__ __nv_bfloat16 g_wdobj_hi[HH * PP];
__device__ __nv_bfloat16 g_wdobj_lo[HH * PP];
__device__ __nv_bfloat16 g_wdrel_hi[HH * PP];
__device__ __nv_bfloat16 g_wdrel_lo[HH * PP];
__device__ __nv_bfloat16 g_wg_hi[4 * FF * 2 * HH];
__device__ __nv_bfloat16 g_wg_lo[4 * FF * 2 * HH];
__device__ __nv_bfloat16 g_wf_hi[4 * HH * HH];  // wih_objf, whh_objf, wih_relf, whh_relf
__device__ __nv_bfloat16 g_wf_lo[4 * HH * HH];

// ======================= weight prep: W[K,N] -> hi/lo bf16 [N][K] =======================
__global__ void transpose_split(const float* __restrict__ W, int K, int N,
                                __nv_bfloat16* __restrict__ hi, __nv_bfloat16* __restrict__ lo)
{
    __shared__ float tile[32][33];
    int n0 = blockIdx.x * 32, k0 = blockIdx.y * 32;
    int tx = threadIdx.x, ty = threadIdx.y;   // (32, 8)
#pragma unroll
    for (int i = 0; i < 32; i += 8)
        tile[ty + i][tx] = W[(size_t)(k0 + ty + i) * N + n0 + tx];
    __syncthreads();
#pragma unroll
    for (int i = 0; i < 32; i += 8) {
        float v = tile[tx][ty + i];
        __nv_bfloat16 h = __float2bfloat16_rn(v);
        size_t o = (size_t)(n0 + ty + i) * K + k0 + tx;
        hi[o] = h;
        lo[o] = __float2bfloat16_rn(v - __bfloat162float(h));
    }
}

// ======================= bf16x3 mma.sync GEMM (R9 mainloop, BK=32) =======================
// C[M,N] = f(A) @ B^T + bias1 (+bias2), f = id / relu, virtual K = K1(+K2).
// A fp32; B pre-split bf16 hi/lo, [N][ldB] row-major.
template<int BN, bool DUAL, bool RELU_A>
__global__ __launch_bounds__(256, 1)
void gemm_mma(const float* __restrict__ A1, int ldA1, int K1,
              const float* __restrict__ A2, int ldA2, int K2,
              const __nv_bfloat16* __restrict__ Bhi1, const __nv_bfloat16* __restrict__ Blo1, int ldB1,
              const __nv_bfloat16* __restrict__ Bhi2, const __nv_bfloat16* __restrict__ Blo2, int ldB2,
              const float* __restrict__ bias1, const float* __restrict__ bias2,
              float* __restrict__ C, int ldC, int reluC)
{
    constexpr int WARPS_M = 2;
    constexpr int WM = 128 / WARPS_M;          // 64
    constexpr int MT = WM / 16;                // 4
    constexpr int NT = 4;                      // WN = 32
    constexpr int AST = 40;                    // smem row stride in halves (80B)
    constexpr int A_HALVES = 128 * AST;
    constexpr int B_HALVES = BN * AST;
    constexpr int STAGE = 2 * A_HALVES + 2 * B_HALVES;
    constexpr int NB = (BN * 4) / 256;

    extern __shared__ __nv_bfloat16 sm[];
    const int t = threadIdx.x;
    const int wid = t >> 5, lane = t & 31;
    const int wm = wid % WARPS_M, wn = wid / WARPS_M;

    const int blockM = blockIdx.y * 128;
    const int n0 = blockIdx.x * BN;

    const int arow = t >> 1, ahalf = t & 1;
    const int row_m = blockM + arow;
    const float* rowA1 = A1 + (size_t)row_m * ldA1;
    const float* rowA2 = DUAL ? (A2 + (size_t)row_m * ldA2) : A1;

    const int nChunks = (K1 + (DUAL ? K2 : 0)) / 32;

    const int a_row_off = (lane & 7) | (((lane >> 3) & 1) << 3);
    const int a_kh = (lane >> 4) << 3;
    const int b_row_off = lane & 7;
    const int b_kh = ((lane >> 3) & 1) << 3;

    float acc[MT][NT][4];
#pragma unroll
    for (int i = 0; i < MT; i++)
#pragma unroll
        for (int j = 0; j < NT; j++)
#pragma unroll
            for (int k = 0; k < 4; k++) acc[i][j][k] = 0.f;

    float fA[16];
    uint4 bHiS[NB], bLoS[NB];

    auto loadA = [&](int c) {
        int k0v = c * 32;
        bool fh = (!DUAL) || (k0v < K1);
        const float* src = (fh ? rowA1 + k0v : rowA2 + (k0v - K1)) + ahalf * 16;
#pragma unroll
        for (int q = 0; q < 4; q++) {
            float4 v = ((const float4*)src)[q];
            if (RELU_A) {
                v.x = fmaxf(v.x, 0.f); v.y = fmaxf(v.y, 0.f);
                v.z = fmaxf(v.z, 0.f); v.w = fmaxf(v.w, 0.f);
            }
            fA[q * 4 + 0] = v.x; fA[q * 4 + 1] = v.y;
            fA[q * 4 + 2] = v.z; fA[q * 4 + 3] = v.w;
        }
    };
    auto loadB = [&](int c) {
        int k0v = c * 32;
        bool fh = (!DUAL) || (k0v < K1);
        const __nv_bfloat16* bh = fh ? Bhi1 : Bhi2;
        const __nv_bfloat16* bl = fh ? Blo1 : Blo2;
        int ldB = fh ? ldB1 : ldB2;
        int kk = fh ? k0v : (k0v - K1);
#pragma unroll
        for (int i = 0; i < NB; i++) {
            int idx = t + i * 256;
            int row = idx >> 2, q = idx & 3;
            const __nv_bfloat16* p = bh + (size_t)(n0 + row) * ldB + kk;
            const __nv_bfloat16* pl = bl + (size_t)(n0 + row) * ldB + kk;
            bHiS[i] = ((const uint4*)p)[q];
            bLoS[i] = ((const uint4*)pl)[q];
        }
    };
    auto storeA = [&](int buf) {
        __nv_bfloat16* sA = sm + buf * STAGE;
        __nv_bfloat16* sAlo = sA + A_HALVES;
        uint32_t h[8], l[8];
#pragma unroll
        for (int i = 0; i < 8; i++) {
            float v0 = fA[2 * i], v1 = fA[2 * i + 1];
            __nv_bfloat16 h0 = __float2bfloat16_rn(v0), h1 = __float2bfloat16_rn(v1);
            __nv_bfloat162 hp; hp.x = h0; hp.y = h1;
            h[i] = *reinterpret_cast<uint32_t*>(&hp);
            l[i] = pack_bf16(v0 - __bfloat162float(h0), v1 - __bfloat162float(h1));
        }
        int base = arow * AST + ahalf * 16;
        *(uint4*)(sA + base)       = make_uint4(h[0], h[1], h[2], h[3]);
        *(uint4*)(sA + base + 8)   = make_uint4(h[4], h[5], h[6], h[7]);
        *(uint4*)(sAlo + base)     = make_uint4(l[0], l[1], l[2], l[3]);
        *(uint4*)(sAlo + base + 8) = make_uint4(l[4], l[5], l[6], l[7]);
    };
    auto storeB = [&](int buf) {
        __nv_bfloat16* sB = sm + buf * STAGE + 2 * A_HALVES;
        __nv_bfloat16* sBlo = sB + B_HALVES;
#pragma unroll
        for (int i = 0; i < NB; i++) {
            int idx = t + i * 256;
            int row = idx >> 2, q = idx & 3;
            ((uint4*)(sB + row * AST))[q] = bHiS[i];
            ((uint4*)(sBlo + row * AST))[q] = bLoS[i];
        }
    };
    auto domma = [&](int buf) {
        uint32_t aHi = smem_u32(sm + buf * STAGE);
        uint32_t aLo = aHi + A_HALVES * 2;
        uint32_t bHi = aHi + 2 * A_HALVES * 2;
        uint32_t bLo = bHi + B_HALVES * 2;
#pragma unroll
        for (int ks = 0; ks < 2; ks++) {
            uint32_t ah[MT][4], al[MT][4], bh[NT][2], bl[NT][2];
#pragma unroll
            for (int mt = 0; mt < MT; mt++) {
                uint32_t off = (uint32_t)((wm * WM + mt * 16 + a_row_off) * AST + ks * 16 + a_kh) * 2;
                ldsm_x4(ah[mt], aHi + off);
                ldsm_x4(al[mt], aLo + off);
            }
#pragma unroll
            for (int nt = 0; nt < NT; nt++) {
                uint32_t off = (uint32_t)((wn * 32 + nt * 8 + b_row_off) * AST + ks * 16 + b_kh) * 2;
                ldsm_x2(bh[nt], bHi + off);
                ldsm_x2(bl[nt], bLo + off);
            }
#pragma unroll
            for (int mt = 0; mt < MT; mt++)
#pragma unroll
                for (int nt = 0; nt < NT; nt++) mma_bf16(acc[mt][nt], ah[mt], bh[nt]);
#pragma unroll
            for (int mt = 0; mt < MT; mt++)
#pragma unroll
                for (int nt = 0; nt < NT; nt++) mma_bf16(acc[mt][nt], ah[mt], bl[nt]);
#pragma unroll
            for (int mt = 0; mt < MT; mt++)
#pragma unroll
                for (int nt = 0; nt < NT; nt++) mma_bf16(acc[mt][nt], al[mt], bh[nt]);
        }
    };

    loadA(0); loadB(0);
    storeA(0); storeB(0);
    __syncthreads();
    for (int c = 0; c < nChunks; c++) {
        if (c + 1 < nChunks) { loadA(c + 1); loadB(c + 1); }
        domma(c & 1);
        if (c + 1 < nChunks) { storeA((c + 1) & 1); storeB((c + 1) & 1); }
        __syncthreads();
    }

#pragma unroll
    for (int nt = 0; nt < NT; nt++) {
        int col = n0 + wn * 32 + nt * 8 + (lane & 3) * 2;
        float b0 = bias1 ? bias1[col] : 0.f;
        float b1 = bias1 ? bias1[col + 1] : 0.f;
        if (bias2) { b0 += bias2[col]; b1 += bias2[col + 1]; }
#pragma unroll
        for (int mt = 0; mt < MT; mt++) {
            int r0 = blockM + wm * WM + mt * 16 + (lane >> 2);
            float2 o0, o1;
            o0.x = acc[mt][nt][0] + b0; o0.y = acc[mt][nt][1] + b1;
            o1.x = acc[mt][nt][2] + b0; o1.y = acc[mt][nt][3] + b1;
            if (reluC) {
                o0.x = fmaxf(o0.x, 0.f); o0.y = fmaxf(o0.y, 0.f);
                o1.x = fmaxf(o1.x, 0.f); o1.y = fmaxf(o1.y, 0.f);
            }
            *(float2*)(C + (size_t)r0 * ldC + col) = o0;
            *(float2*)(C + (size_t)(r0 + 8) * ldC + col) = o1;
        }
    }
}

// ======================= merged gate kernel: all 4 MPUs in one launch =======================
// blockIdx.x = gate id. A = relu(LN(concat(first, second))) per gate, B = [64][2048] hi/lo.
// Epilogue computes gate[e] = mean_f sigmoid(D[e,f] + bias[f]) in-kernel.
struct GateParams {
    const float* A1[4]; const int* idx1[4];
    const float* A2[4]; const int* idx2[4];
    const __nv_bfloat16* Bh[4]; const __nv_bfloat16* Bl[4];
    const float* mu[4]; const float* rs[4];
    const float* lng[4]; const float* lnb[4]; const float* bias[4];
    float* gate[4];
};

__global__ __launch_bounds__(256, 1)
void gate_mma(GateParams P)
{
    constexpr int WARPS_M = 4;
    constexpr int WM = 32;
    constexpr int MT = 2;
    constexpr int NT = 4;
    constexpr int BN = 64;
    constexpr int AST = 40;
    constexpr int A_HALVES = 128 * AST;
    constexpr int B_HALVES = BN * AST;
    constexpr int STAGE = 2 * A_HALVES + 2 * B_HALVES;

    extern __shared__ __nv_bfloat16 sm[];
    __shared__ float red[128][2];
    const int g = blockIdx.x;
    const int t = threadIdx.x;
    const int wid = t >> 5, lane = t & 31;
    const int wm = wid & 3, wn = wid >> 2;

    const int blockM = blockIdx.y * 128;
    const int arow = t >> 1, ahalf = t & 1;
    const int row_m = blockM + arow;
    const int r1 = P.idx1[g] ? P.idx1[g][row_m] : row_m;
    const int r2 = P.idx2[g] ? P.idx2[g][row_m] : row_m;
    const float mu_t = P.mu[g][row_m], rs_t = P.rs[g][row_m];
    const float* rowA1 = P.A1[g] + (size_t)r1 * HH;
    const float* rowA2 = P.A2[g] + (size_t)r2 * HH;
    const __nv_bfloat16* Bh = P.Bh[g];
    const __nv_bfloat16* Bl = P.Bl[g];
    const float* lng = P.lng[g];
    const float* lnb = P.lnb[g];

    const int nChunks = (2 * HH) / 32;   // 64

    const int a_row_off = (lane & 7) | (((lane >> 3) & 1) << 3);
    const int a_kh = (lane >> 4) << 3;
    const int b_row_off = lane & 7;
    const int b_kh = ((lane >> 3) & 1) << 3;

    float acc[MT][NT][4];
#pragma unroll
    for (int i = 0; i < MT; i++)
#pragma unroll
        for (int j = 0; j < NT; j++)
#pragma unroll
            for (int k = 0; k < 4; k++) acc[i][j][k] = 0.f;

    float fA[16];
    uint4 bHiS, bLoS;

    auto loadA = [&](int c) {
        int k0v = c * 32;
        bool fh = (k0v < HH);
        const float* src = (fh ? rowA1 + k0v : rowA2 + (k0v - HH)) + ahalf * 16;
        int jb = k0v + ahalf * 16;
#pragma unroll
        for (int q = 0; q < 4; q++) {
            float4 v = ((const float4*)src)[q];
            int j = jb + q * 4;
            float4 gg = *(const float4*)(lng + j);
            float4 bb = *(const float4*)(lnb + j);
            v.x = fmaxf(fmaf((v.x - mu_t) * rs_t, gg.x, bb.x), 0.f);
            v.y = fmaxf(fmaf((v.y - mu_t) * rs_t, gg.y, bb.y), 0.f);
            v.z = fmaxf(fmaf((v.z - mu_t) * rs_t, gg.z, bb.z), 0.f);
            v.w = fmaxf(fmaf((v.w - mu_t) * rs_t, gg.w, bb.w), 0.f);
            fA[q * 4 + 0] = v.x; fA[q * 4 + 1] = v.y;
            fA[q * 4 + 2] = v.z; fA[q * 4 + 3] = v.w;
        }
    };
    auto loadB = [&](int c) {
        int k0v = c * 32;
        int row = t >> 2, q = t & 3;   // 64 rows x 4 chunks = 256
        size_t go = (size_t)row * (2 * HH) + k0v;
        bHiS = ((const uint4*)(Bh + go))[q];
        bLoS = ((const uint4*)(Bl + go))[q];
    };
    auto storeA = [&](int buf) {
        __nv_bfloat16* sA = sm + buf * STAGE;
        __nv_bfloat16* sAlo = sA + A_HALVES;
        uint32_t h[8], l[8];
#pragma unroll
        for (int i = 0; i < 8; i++) {
            float v0 = fA[2 * i], v1 = fA[2 * i + 1];
            __nv_bfloat16 h0 = __float2bfloat16_rn(v0), h1 = __float2bfloat16_rn(v1);
            __nv_bfloat162 hp; hp.x = h0; hp.y = h1;
            h[i] = *reinterpret_cast<uint32_t*>(&hp);
            l[i] = pack_bf16(v0 - __bfloat162float(h0), v1 - __bfloat162float(h1));
        }
        int base = arow * AST + ahalf * 16;
        *(uint4*)(sA + base)       = make_uint4(h[0], h[1], h[2], h[3]);
        *(uint4*)(sA + base + 8)   = make_uint4(h[4], h[5], h[6], h[7]);
        *(uint4*)(sAlo + base)     = make_uint4(l[0], l[1], l[2], l[3]);
        *(uint4*)(sAlo + base + 8) = make_uint4(l[4], l[5], l[6], l[7]);
    };
    auto storeB = [&](int buf) {
        __nv_bfloat16* sB = sm + buf * STAGE + 2 * A_HALVES;
        __nv_bfloat16* sBlo = sB + B_HALVES;
        int row = t >> 2, q = t & 3;
        ((uint4*)(sB + row * AST))[q] = bHiS;
        ((uint4*)(sBlo + row * AST))[q] = bLoS;
    };
    auto domma = [&](int buf) {
        uint32_t aHi = smem_u32(sm + buf * STAGE);
        uint32_t aLo = aHi + A_HALVES * 2;
        uint32_t bHi = aHi + 2 * A_HALVES * 2;
        uint32_t bLo = bHi + B_HALVES * 2;
#pragma unroll
        for (int ks = 0; ks < 2; ks++) {
            uint32_t ah[MT][4], al[MT][4], bh[NT][2], bl[NT][2];
#pragma unroll
            for (int mt = 0; mt < MT; mt++) {
                uint32_t off = (uint32_t)((wm * WM + mt * 16 + a_row_off) * AST + ks * 16 + a_kh) * 2;
                ldsm_x4(ah[mt], aHi + off);
                ldsm_x4(al[mt], aLo + off);
            }
#pragma unroll
            for (int nt = 0; nt < NT; nt++) {
                uint32_t off = (uint32_t)((wn * 32 + nt * 8 + b_row_off) * AST + ks * 16 + b_kh) * 2;
                ldsm_x2(bh[nt], bHi + off);
                ldsm_x2(bl[nt], bLo + off);
            }
#pragma unroll
            for (int mt = 0; mt < MT; mt++)
#pragma unroll
                for (int nt = 0; nt < NT; nt++) mma_bf16(acc[mt][nt], ah[mt], bh[nt]);
#pragma unroll
            for (int mt = 0; mt < MT; mt++)
#pragma unroll
                for (int nt = 0; nt < NT; nt++) mma_bf16(acc[mt][nt], ah[mt], bl[nt]);
#pragma unroll
            for (int mt = 0; mt < MT; mt++)
#pragma unroll
                for (int nt = 0; nt < NT; nt++) mma_bf16(acc[mt][nt], al[mt], bh[nt]);
        }
    };

    loadA(0); loadB(0);
    storeA(0); storeB(0);
    __syncthreads();
    for (int c = 0; c < nChunks; c++) {
        if (c + 1 < nChunks) { loadA(c + 1); loadB(c + 1); }
        domma(c & 1);
        if (c + 1 < nChunks) { storeA((c + 1) & 1); storeB((c + 1) & 1); }
        __syncthreads();
    }

    // ---- fused gate epilogue: mean_f sigmoid(acc + bias) ----
    const float* bias = P.bias[g];
    float pr[4];   // rows: wm*32 + {lr, lr+8, lr+16, lr+24}
#pragma unroll
    for (int mt = 0; mt < MT; mt++) {
        float pa = 0.f, pb = 0.f;
#pragma unroll
        for (int nt = 0; nt < NT; nt++) {
            int col = wn * 32 + nt * 8 + (lane & 3) * 2;
            float b0 = bias[col], b1 = bias[col + 1];
            pa += 1.f / (1.f + __expf(-(acc[mt][nt][0] + b0)));
            pa += 1.f / (1.f + __expf(-(acc[mt][nt][1] + b1)));
            pb += 1.f / (1.f + __expf(-(acc[mt][nt][2] + b0)));
            pb += 1.f / (1.f + __expf(-(acc[mt][nt][3] + b1)));
        }
        pr[mt * 2] = pa; pr[mt * 2 + 1] = pb;
    }
#pragma unroll
    for (int o = 1; o <= 2; o <<= 1)
#pragma unroll
        for (int i = 0; i < 4; i++)
            pr[i] += __shfl_xor_sync(0xffffffffu, pr[i], o);
    if ((lane & 3) == 0) {
        int rbase = wm * 32 + (lane >> 2);
        red[rbase][wn]      = pr[0];
        red[rbase + 8][wn]  = pr[1];
        red[rbase + 16][wn] = pr[2];
        red[rbase + 24][wn] = pr[3];
    }
    __syncthreads();
    if (t < 128)
        P.gate[g][blockM + t] = (red[t][0] + red[t][1]) * (1.f / 64.f);
}

// ======================= elementwise kernels (validated in R2) =======================
__global__ void rowstats_kernel(const float* __restrict__ X, float* __restrict__ sum,
                                float* __restrict__ sq, int rows)
{
    int row = blockIdx.x * 8 + (threadIdx.x >> 5);
    int lane = threadIdx.x & 31;
    if (row >= rows) return;
    const float4* p = (const float4*)(X + (size_t)row * HH);
    float s = 0.f, q = 0.f;
#pragma unroll
    for (int i = 0; i < 8; i++) {
        float4 v = p[lane + (i << 5)];
        s += v.x + v.y + v.z + v.w;
        q += v.x * v.x + v.y * v.y + v.z * v.z + v.w * v.w;
    }
#pragma unroll
    for (int o = 16; o > 0; o >>= 1) {
        s += __shfl_down_sync(0xffffffffu, s, o);
        q += __shfl_down_sync(0xffffffffu, q, o);
    }
    if (lane == 0) { sum[row] = s; sq[row] = q; }
}

__global__ void edge_stats_kernel(const int* __restrict__ sub, const int* __restrict__ obj,
    const float* __restrict__ sR, const float* __restrict__ qR,
    const float* __restrict__ sO, const float* __restrict__ qO,
    float* __restrict__ muS, float* __restrict__ rsS,
    float* __restrict__ muO, float* __restrict__ rsO)
{
    int e = blockIdx.x * 256 + threadIdx.x;
    if (e >= EE) return;
    float sr = sR[e], qr = qR[e];
    {
        int n = sub[e];
        float s = sr + sO[n], q = qr + qO[n];
        float m = s * (1.f / 2048.f);
        float v = q * (1.f / 2048.f) - m * m;
        muS[e] = m; rsS[e] = rsqrtf(v + 1e-5f);
    }
    {
        int n = obj[e];
        float s = sr + sO[n], q = qr + qO[n];
        float m = s * (1.f / 2048.f);
        float v = q * (1.f / 2048.f) - m * m;
        muO[e] = m; rsO[e] = rsqrtf(v + 1e-5f);
    }
}

__global__ void rel_msg_kernel(const float* __restrict__ obj,
                               const int* __restrict__ sub, const int* __restrict__ objx,
                               const float* __restrict__ gS, const float* __restrict__ gO,
                               float* __restrict__ out)
{
    int i = blockIdx.x * 256 + threadIdx.x;
    int e = i >> 8;
    int h4 = (i & 255) << 2;
    float4 a = *(const float4*)(obj + (size_t)sub[e]  * HH + h4);
    float4 b = *(const float4*)(obj + (size_t)objx[e] * HH + h4);
    float ga = 0.5f * gS[e], gb = 0.5f * gO[e];
    float4 r;
    r.x = ga * a.x + gb * b.x;
    r.y = ga * a.y + gb * b.y;
    r.z = ga * a.z + gb * b.z;
    r.w = ga * a.w + gb * b.w;
    *(float4*)(out + (size_t)e * HH + h4) = r;
}

__global__ void scatter_kernel(const float* __restrict__ rel,
                               const int* __restrict__ sub, const int* __restrict__ objx,
                               const float* __restrict__ gS, const float* __restrict__ gO,
                               float* __restrict__ accS, float* __restrict__ accO)
{
    int i = blockIdx.x * 256 + threadIdx.x;
    int e = i >> 8;
    int h4 = (i & 255) << 2;
    float4 v = *(const float4*)(rel + (size_t)e * HH + h4);
    float gs = gS[e], go = gO[e];
    float* ps = accS + (size_t)sub[e] * HH + h4;
    atomicAdd(ps + 0, v.x * gs);
    atomicAdd(ps + 1, v.y * gs);
    atomicAdd(ps + 2, v.z * gs);
    atomicAdd(ps + 3, v.w * gs);
    float* po = accO + (size_t)objx[e] * HH + h4;
    atomicAdd(po + 0, v.x * go);
    atomicAdd(po + 1, v.y * go);
    atomicAdd(po + 2, v.z * go);
    atomicAdd(po + 3, v.w * go);
}

__global__ void objmsg_kernel(const float* __restrict__ accS, const float* __restrict__ accO,
                              const float* __restrict__ cS, const float* __restrict__ cO,
                              float* __restrict__ out)
{
    int i = blockIdx.x * 256 + threadIdx.x;
    int n = i >> 8;
    int h4 = (i & 255) << 2;
    float rs_ = 0.5f / fmaxf(cS[n], 1.f);
    float ro_ = 0.5f / fmaxf(cO[n], 1.f);
    float4 a = *(const float4*)(accS + (size_t)n * HH + h4);
    float4 b = *(const float4*)(accO + (size_t)n * HH + h4);
    float4 r;
    r.x = rs_ * a.x + ro_ * b.x;
    r.y = rs_ * a.y + ro_ * b.y;
    r.z = rs_ * a.z + ro_ * b.z;
    r.w = rs_ * a.w + ro_ * b.w;
    *(float4*)(out + (size_t)n * HH + h4) = r;
}

__global__ void zero_kernel(float* __restrict__ p, int n4)
{
    int i = blockIdx.x * 256 + threadIdx.x;
    if (i < n4) *(float4*)(p + (size_t)i * 4) = make_float4(0.f, 0.f, 0.f, 0.f);
}

__global__ void count_kernel(const int* __restrict__ sub, const int* __restrict__ objx,
                             float* __restrict__ cS, float* __restrict__ cO)
{
    int e = blockIdx.x * 256 + threadIdx.x;
    if (e < EE) {
        atomicAdd(&cS[sub[e]], 1.f);
        atomicAdd(&cO[objx[e]], 1.f);
    }
}

// ======================= host driver =======================
template<typename T>
static T* symaddrT(const void* sym)
{
    void* p = nullptr;
    cudaGetSymbolAddress(&p, sym);
    return (T*)p;
}

extern "C" void kernel_launch(void* const* d_in, const int* in_sizes, int n_in,
                              void* d_out, int out_size)
{
    const float* obj_feat   = (const float*)d_in[0];
    const float* rel_feat   = (const float*)d_in[1];
    const int*   sub_idx    = (const int*)d_in[2];
    const int*   obj_idx    = (const int*)d_in[3];
    const float* w_obj_down = (const float*)d_in[4];
    const float* b_obj_down = (const float*)d_in[5];
    const float* w_rel_down = (const float*)d_in[6];
    const float* b_rel_down = (const float*)d_in[7];
    const float *ln_g[4], *ln_b[4], *w_m[4], *b_m[4];
    for (int m = 0; m < 4; m++) {       // 0=s2p, 1=o2p, 2=p2s, 3=p2o
        ln_g[m] = (const float*)d_in[8 + 4 * m];
        ln_b[m] = (const float*)d_in[9 + 4 * m];
        w_m[m]  = (const float*)d_in[10 + 4 * m];
        b_m[m]  = (const float*)d_in[11 + 4 * m];
    }
    const float* wf[4]  = { (const float*)d_in[24], (const float*)d_in[26],
                            (const float*)d_in[28], (const float*)d_in[30] };
    const float* bih_objf = (const float*)d_in[25];
    const float* bhh_objf = (const float*)d_in[27];
    const float* bih_relf = (const float*)d_in[29];
    const float* bhh_relf = (const float*)d_in[31];
    float* out = (float*)d_out;

    float* obj0    = symaddrT<float>(g_obj0);
    float* objA    = symaddrT<float>(g_objA);
    float* rel0    = symaddrT<float>(g_rel0);
    float* relA    = symaddrT<float>(g_relA);
    float* relmsg  = symaddrT<float>(g_relmsg);
    float* objmsg  = symaddrT<float>(g_objmsg);
    float* accS    = symaddrT<float>(g_accS);
    float* accO    = symaddrT<float>(g_accO);
    float* cntS    = symaddrT<float>(g_cntS);
    float* cntO    = symaddrT<float>(g_cntO);
    float* rsumR   = symaddrT<float>(g_rsumR);
    float* rsqR    = symaddrT<float>(g_rsqR);
    float* rsumO   = symaddrT<float>(g_rsumO);
    float* rsqO    = symaddrT<float>(g_rsqO);
    float* muS     = symaddrT<float>(g_muS);
    float* rsS     = symaddrT<float>(g_rsS);
    float* muO     = symaddrT<float>(g_muO);
    float* rsO     = symaddrT<float>(g_rsO);
    float* gate[4] = { symaddrT<float>(g_gate0), symaddrT<float>(g_gate1),
                       symaddrT<float>(g_gate2), symaddrT<float>(g_gate3) };
    __nv_bfloat16* wdobj_hi = symaddrT<__nv_bfloat16>(g_wdobj_hi);
    __nv_bfloat16* wdobj_lo = symaddrT<__nv_bfloat16>(g_wdobj_lo);
    __nv_bfloat16* wdrel_hi = symaddrT<__nv_bfloat16>(g_wdrel_hi);
    __nv_bfloat16* wdrel_lo = symaddrT<__nv_bfloat16>(g_wdrel_lo);
    __nv_bfloat16* wg_hi    = symaddrT<__nv_bfloat16>(g_wg_hi);
    __nv_bfloat16* wg_lo    = symaddrT<__nv_bfloat16>(g_wg_lo);
    __nv_bfloat16* wf_hi    = symaddrT<__nv_bfloat16>(g_wf_hi);
    __nv_bfloat16* wf_lo    = symaddrT<__nv_bfloat16>(g_wf_lo);

    // ---- weight prep ----
    {
        dim3 blk(32, 8);
        transpose_split<<<dim3(HH / 32, PP / 32), blk>>>(w_obj_down, PP, HH, wdobj_hi, wdobj_lo);
        transpose_split<<<dim3(HH / 32, PP / 32), blk>>>(w_rel_down, PP, HH, wdrel_hi, wdrel_lo);
        for (int m = 0; m < 4; m++)
            transpose_split<<<dim3(FF / 32, 2 * HH / 32), blk>>>(
                w_m[m], 2 * HH, FF,
                wg_hi + (size_t)m * FF * 2 * HH, wg_lo + (size_t)m * FF * 2 * HH);
        for (int m = 0; m < 4; m++)
            transpose_split<<<dim3(HH / 32, HH / 32), blk>>>(
                wf[m], HH, HH,
                wf_hi + (size_t)m * HH * HH, wf_lo + (size_t)m * HH * HH);
    }

    // dynamic smem (R9 sizes): double-buffered (A hi/lo + B hi/lo), 80B rows
    constexpr int SM128 = 2 * (2 * 128 * 40 + 2 * 128 * 40) * 2;   // 81920 B
    constexpr int SM64  = 2 * (2 * 128 * 40 + 2 * 64 * 40) * 2;    // 61440 B
    auto kPlain = gemm_mma<128, false, false>;
    auto kFuse  = gemm_mma<128, true,  true>;
    cudaFuncSetAttribute(kPlain, cudaFuncAttributeMaxDynamicSharedMemorySize, SM128);
    cudaFuncSetAttribute(kFuse,  cudaFuncAttributeMaxDynamicSharedMemorySize, SM128);
    cudaFuncSetAttribute(gate_mma, cudaFuncAttributeMaxDynamicSharedMemorySize, SM64);

    // ---- down-dim projections: relu(X @ Wd + b) ----
    kPlain<<<dim3(HH / 128, NN / 128), 256, SM128>>>(
        obj_feat, PP, PP, nullptr, 0, 0,
        wdobj_hi, wdobj_lo, PP, nullptr, nullptr, 0,
        b_obj_down, nullptr, obj0, HH, 1);
    kPlain<<<dim3(HH / 128, EE / 128), 256, SM128>>>(
        rel_feat, PP, PP, nullptr, 0, 0,
        wdrel_hi, wdrel_lo, PP, nullptr, nullptr, 0,
        b_rel_down, nullptr, rel0, HH, 1);

    // ---- per-node edge counts ----
    zero_kernel<<<(NN / 4 + 255) / 256, 256>>>(cntS, NN / 4);
    zero_kernel<<<(NN / 4 + 255) / 256, 256>>>(cntO, NN / 4);
    count_kernel<<<EE / 256, 256>>>(sub_idx, obj_idx, cntS, cntO);

    float* objCur = obj0;
    float* relCur = rel0;
    for (int it = 0; it < 2; it++) {
        float* objNext = (it == 0) ? objA : out;
        float* relNext = (it == 0) ? relA : out + (size_t)NN * HH;

        // LN stats (shared across the 4 MPUs)
        rowstats_kernel<<<EE / 8, 256>>>(relCur, rsumR, rsqR, EE);
        rowstats_kernel<<<NN / 8, 256>>>(objCur, rsumO, rsqO, NN);
        edge_stats_kernel<<<EE / 256, 256>>>(sub_idx, obj_idx, rsumR, rsqR,
                                             rsumO, rsqO, muS, rsS, muO, rsO);

        // ---- all 4 gates in ONE launch (fused sigmoid-mean epilogue) ----
        GateParams gp;
        const float* fsrc[4]  = { relCur, relCur, objCur, objCur };
        const int*   fidx[4]  = { nullptr, nullptr, sub_idx, obj_idx };
        const float* ssrc[4]  = { objCur, objCur, relCur, relCur };
        const int*   sidx[4]  = { sub_idx, obj_idx, nullptr, nullptr };
        const float* gmu[4]   = { muS, muO, muS, muO };
        const float* grs[4]   = { rsS, rsO, rsS, rsO };
        for (int m = 0; m < 4; m++) {
            gp.A1[m] = fsrc[m]; gp.idx1[m] = fidx[m];
            gp.A2[m] = ssrc[m]; gp.idx2[m] = sidx[m];
            gp.Bh[m] = wg_hi + (size_t)m * FF * 2 * HH;
            gp.Bl[m] = wg_lo + (size_t)m * FF * 2 * HH;
            gp.mu[m] = gmu[m]; gp.rs[m] = grs[m];
            gp.lng[m] = ln_g[m]; gp.lnb[m] = ln_b[m];
            gp.bias[m] = b_m[m]; gp.gate[m] = gate[m];
        }
        gate_mma<<<dim3(4, EE / 128), 256, SM64>>>(gp);

        // messages
        rel_msg_kernel<<<EE * (HH / 4) / 256, 256>>>(objCur, sub_idx, obj_idx,
                                                     gate[0], gate[1], relmsg);
        zero_kernel<<<(NN * HH / 4 + 255) / 256, 256>>>(accS, NN * HH / 4);
        zero_kernel<<<(NN * HH / 4 + 255) / 256, 256>>>(accO, NN * HH / 4);
        scatter_kernel<<<EE * (HH / 4) / 256, 256>>>(relCur, sub_idx, obj_idx,
                                                     gate[2], gate[3], accS, accO);
        objmsg_kernel<<<NN * (HH / 4) / 256, 256>>>(accS, accO, cntS, cntO, objmsg);

        // fusion: C = relu(msg)@Wih + relu(cur)@Whh + bih + bhh
        kFuse<<<dim3(HH / 128, NN / 128), 256, SM128>>>(
            objmsg, HH, HH, objCur, HH, HH,
            wf_hi + 0 * (size_t)HH * HH, wf_lo + 0 * (size_t)HH * HH, HH,
            wf_hi + 1 * (size_t)HH * HH, wf_lo + 1 * (size_t)HH * HH, HH,
            bih_objf, bhh_objf, objNext, HH, 0);
        kFuse<<<dim3(HH / 128, EE / 128), 256, SM128>>>(
            relmsg, HH, HH, relCur, HH, HH,
            wf_hi + 2 * (size_t)HH * HH, wf_lo + 2 * (size_t)HH * HH, HH,
            wf_hi + 3 * (size_t)HH * HH, wf_lo + 3 * (size_t)HH * HH, HH,
            bih_relf, bhh_relf, relNext, HH, 0);

        objCur = objNext;
        relCur = relNext;
    }
}